// round 1
// baseline (speedup 1.0000x reference)
#include <cuda_runtime.h>
#include <cuda_bf16.h>
#include <cstdint>

// Problem constants (from reference): B = 512 embeddings, D = 512 dims,
// MARGIN = 0.2, NUM_IDS = 64. Output = scalar mean semi-hard triplet loss.
#define NB 512
#define ND 512
#define MARGIN 0.2f
#define INF_F 1e30f

// ---------------- scratch (no allocations allowed) ----------------
__device__ float g_Dm[NB * NB];   // pairwise squared distances (1 MB, L2-resident)
__device__ float g_sq[NB];        // row squared norms
__device__ float g_psum[NB];      // per-anchor loss partial sums
__device__ int   g_pcnt[NB];      // per-anchor valid-pair counts

// ---------------- kernel 1: row squared norms ----------------
// grid 64 x 256 threads, one warp per row (64*8 = 512 rows)
__global__ void k_rowsq(const float* __restrict__ E) {
    int warp = threadIdx.x >> 5, lane = threadIdx.x & 31;
    int r = blockIdx.x * 8 + warp;
    const float* row = E + r * ND;
    float s = 0.f;
#pragma unroll
    for (int k = lane; k < ND; k += 32) { float v = row[k]; s += v * v; }
#pragma unroll
    for (int off = 16; off > 0; off >>= 1)
        s += __shfl_xor_sync(0xFFFFFFFFu, s, off);
    if (lane == 0) g_sq[r] = s;
}

// ---------------- kernel 2: tiled SGEMM (C = E E^T) -> Dm ----------------
// 64x64 tiles, BK=32, 256 threads, 4x4 per thread. grid (8,8).
__global__ void __launch_bounds__(256) k_dist(const float* __restrict__ E) {
    __shared__ float As[64][33];   // [row-in-tile][k] (+1 pad: conflict-free stores)
    __shared__ float Bs[64][33];

    const int tid = threadIdx.x;
    const int tx = tid & 15;       // 0..15 -> 4 cols each
    const int ty = tid >> 4;       // 0..15 -> 4 rows each
    const int bi = blockIdx.y;     // row tile
    const int bj = blockIdx.x;     // col tile

    float acc[4][4];
#pragma unroll
    for (int i = 0; i < 4; i++)
#pragma unroll
        for (int j = 0; j < 4; j++) acc[i][j] = 0.f;

    for (int kt = 0; kt < ND; kt += 32) {
        // cooperative load: 64 rows x 32 k-floats per tile = 512 float4, 2 per thread
#pragma unroll
        for (int l = 0; l < 2; l++) {
            int idx = tid + l * 256;
            int row = idx >> 3;          // 0..63
            int kq  = idx & 7;           // 0..7 (x4 floats)
            float4 va = *reinterpret_cast<const float4*>(
                E + (size_t)(bi * 64 + row) * ND + kt + kq * 4);
            float4 vb = *reinterpret_cast<const float4*>(
                E + (size_t)(bj * 64 + row) * ND + kt + kq * 4);
            As[row][kq * 4 + 0] = va.x; As[row][kq * 4 + 1] = va.y;
            As[row][kq * 4 + 2] = va.z; As[row][kq * 4 + 3] = va.w;
            Bs[row][kq * 4 + 0] = vb.x; Bs[row][kq * 4 + 1] = vb.y;
            Bs[row][kq * 4 + 2] = vb.z; Bs[row][kq * 4 + 3] = vb.w;
        }
        __syncthreads();

#pragma unroll
        for (int kk = 0; kk < 32; kk++) {
            float a[4], b[4];
#pragma unroll
            for (int i = 0; i < 4; i++) a[i] = As[ty * 4 + i][kk];
#pragma unroll
            for (int j = 0; j < 4; j++) b[j] = Bs[tx * 4 + j][kk];
#pragma unroll
            for (int i = 0; i < 4; i++)
#pragma unroll
                for (int j = 0; j < 4; j++) acc[i][j] += a[i] * b[j];
        }
        __syncthreads();
    }

    // epilogue: Dm = max(sq_i + sq_j - 2*g, 0)
    float sqr[4], sqc[4];
#pragma unroll
    for (int i = 0; i < 4; i++) sqr[i] = g_sq[bi * 64 + ty * 4 + i];
#pragma unroll
    for (int j = 0; j < 4; j++) sqc[j] = g_sq[bj * 64 + tx * 4 + j];
#pragma unroll
    for (int i = 0; i < 4; i++) {
        int row = bi * 64 + ty * 4 + i;
#pragma unroll
        for (int j = 0; j < 4; j++) {
            int col = bj * 64 + tx * 4 + j;
            float d = sqr[i] + sqc[j] - 2.f * acc[i][j];
            g_Dm[row * NB + col] = fmaxf(d, 0.f);
        }
    }
}

// ---------------- kernel 3: per-anchor semi-hard mining ----------------
// grid 64 x 256 threads: one warp per anchor row. Fully warp-synchronous,
// fixed enumeration order -> deterministic fp sums.
__global__ void __launch_bounds__(256) k_loss(const int* __restrict__ labels) {
    __shared__ int s_lab[NB];
    const int tid = threadIdx.x;
    for (int i = tid; i < NB; i += 256) s_lab[i] = labels[i];
    __syncthreads();

    const int warp = tid >> 5, lane = tid & 31;
    const int a = blockIdx.x * 8 + warp;
    const float* row = g_Dm + a * NB;

    float d[16];
    int lb[16];
#pragma unroll
    for (int t = 0; t < 16; t++) {
        int j = t * 32 + lane;
        d[t] = row[j];
        lb[t] = s_lab[j];
    }
    const int la = s_lab[a];

    // min distance over all negatives of this anchor
    float nmin = INF_F;
#pragma unroll
    for (int t = 0; t < 16; t++)
        if (lb[t] != la) nmin = fminf(nmin, d[t]);
#pragma unroll
    for (int off = 16; off > 0; off >>= 1)
        nmin = fminf(nmin, __shfl_xor_sync(0xFFFFFFFFu, nmin, off));

    float sum = 0.f;
    int cnt = 0;
    const bool has_neg = nmin < 1e29f;

    if (has_neg) {
#pragma unroll 1
        for (int t = 0; t < 16; t++) {
            int j = t * 32 + lane;
            unsigned m = __ballot_sync(0xFFFFFFFFu, (j > a) && (lb[t] == la));
            while (m) {
                int lp = __ffs(m) - 1;
                m &= m - 1;
                float ap  = __shfl_sync(0xFFFFFFFFu, d[t], lp);
                float apM = ap + MARGIN;
                float smin = INF_F;
#pragma unroll
                for (int tt = 0; tt < 16; tt++) {
                    bool semi = (lb[tt] != la) && (d[tt] > ap) && (d[tt] < apM);
                    if (semi) smin = fminf(smin, d[tt]);
                }
#pragma unroll
                for (int off = 16; off > 0; off >>= 1)
                    smin = fminf(smin, __shfl_xor_sync(0xFFFFFFFFu, smin, off));
                float negd = (smin < 1e29f) ? smin : nmin;
                sum += fmaxf(ap - negd + MARGIN, 0.f);
                cnt++;
            }
        }
    }
    if (lane == 0) { g_psum[a] = sum; g_pcnt[a] = cnt; }
}

// ---------------- kernel 4: deterministic final reduce ----------------
__global__ void k_final(float* __restrict__ out) {
    __shared__ float ss[NB];
    __shared__ int   sc[NB];
    const int t = threadIdx.x;  // 512 threads
    ss[t] = g_psum[t];
    sc[t] = g_pcnt[t];
    __syncthreads();
    for (int s = 256; s > 0; s >>= 1) {
        if (t < s) { ss[t] += ss[t + s]; sc[t] += sc[t + s]; }
        __syncthreads();
    }
    if (t == 0) out[0] = ss[0] / fmaxf((float)sc[0], 1.0f);
}

extern "C" void kernel_launch(void* const* d_in, const int* in_sizes, int n_in,
                              void* d_out, int out_size) {
    const float* emb    = (const float*)d_in[0];
    const int*   labels = (const int*)d_in[1];
    float*       out    = (float*)d_out;

    k_rowsq<<<64, 256>>>(emb);
    dim3 grid(8, 8);
    k_dist<<<grid, 256>>>(emb);
    k_loss<<<64, 256>>>(labels);
    k_final<<<1, 512>>>(out);
}